// round 11
// baseline (speedup 1.0000x reference)
#include <cuda_runtime.h>
#include <cuda_bf16.h>
#include <math.h>
#include <stdint.h>

#define S    2048
#define NH   32
#define HD   128
#define HID  4096
#define KEEP 206
#define TOPK 204
#define MV   -1000000000.0f
#define RSQ  0.08838834764831845f   /* 1/sqrt(128) */

typedef __nv_bfloat16 bf16;

// ---------------- device scratch ----------------
static __device__ float g_Q[NH * S * HD];
static __device__ float g_K[NH * S * HD];
static __device__ float g_V[NH * S * HD];
static __device__ float g_AW[NH * S * S];          // masked logits (lower tri valid)
static __device__ float g_rowm[NH * S];
static __device__ float g_rowz[NH * S];
static __device__ float g_scores[NH * S];
static __device__ int   g_kidx[NH * KEEP];
static __device__ float g_Kk[NH * 256 * HD];
static __device__ float g_VkT[NH * HD * 256];
static __device__ float g_awk[NH * S * 256];
static __device__ float g_negc[NH * HD];
static __device__ float g_outpre[S * HID];
static __device__ float g_cos[S * 64];
static __device__ float g_sin[S * 64];

// ---------------- RoPE ----------------
__global__ void rope_table_kernel() {
    int idx = blockIdx.x * blockDim.x + threadIdx.x;
    if (idx >= S * 64) return;
    int s = idx >> 6, i = idx & 63;
    double inv = exp(-((double)i / 64.0) * log(10000.0));
    float ph = (float)s * (float)inv;
    g_cos[idx] = cosf(ph);
    g_sin[idx] = sinf(ph);
}

__global__ void rope_apply_kernel() {
    int idx = blockIdx.x * blockDim.x + threadIdx.x;
    if (idx >= NH * S * 64) return;
    int i = idx & 63;
    int s = (idx >> 6) & (S - 1);
    int h = idx >> 17;
    float c  = g_cos[(s << 6) + i];
    float sn = g_sin[(s << 6) + i];
    size_t base = ((size_t)h * S + s) * HD;
    float a = g_Q[base + i], b = g_Q[base + i + 64];
    g_Q[base + i]      = a * c - b * sn;
    g_Q[base + i + 64] = b * c + a * sn;
    a = g_K[base + i]; b = g_K[base + i + 64];
    g_K[base + i]      = a * c - b * sn;
    g_K[base + i + 64] = b * c + a * sn;
}

// ---------------- pipelined tensor-core NT GEMM, 256x128 tile ----------------
enum { M_PROJ = 0, M_LOGITS = 1, M_SP1 = 2, M_SP2 = 3, M_FINAL = 4 };

__device__ __forceinline__ void ldsm4(uint32_t* r, const void* p) {
    uint32_t addr = (uint32_t)__cvta_generic_to_shared(p);
    asm volatile("ldmatrix.sync.aligned.m8n8.x4.shared.b16 {%0,%1,%2,%3},[%4];\n"
                 : "=r"(r[0]), "=r"(r[1]), "=r"(r[2]), "=r"(r[3]) : "r"(addr));
}
__device__ __forceinline__ void mma16816(float* c, const uint32_t* a, const uint32_t* b) {
    asm volatile("mma.sync.aligned.m16n8k16.row.col.f32.bf16.bf16.f32 "
                 "{%0,%1,%2,%3},{%4,%5,%6,%7},{%8,%9},{%0,%1,%2,%3};\n"
                 : "+f"(c[0]), "+f"(c[1]), "+f"(c[2]), "+f"(c[3])
                 : "r"(a[0]), "r"(a[1]), "r"(a[2]), "r"(a[3]), "r"(b[0]), "r"(b[1]));
}
__device__ __forceinline__ void cpa16(const void* smem, const void* gmem) {
    uint32_t s = (uint32_t)__cvta_generic_to_shared(smem);
    asm volatile("cp.async.ca.shared.global [%0],[%1],16;\n" :: "r"(s), "l"(gmem));
}
__device__ __forceinline__ uint32_t pk2(float a, float b) {
    __nv_bfloat162 t = __float22bfloat162_rn(make_float2(a, b));
    return *(uint32_t*)&t;
}

#define LDA 40
#define OFF_AH 0
#define OFF_AL 20480            // 256*80
#define OFF_BH 40960
#define OFF_BL 51200            // +128*80
#define OFF_STG 61440
#define STG_AF 8192             // 256*32 floats
#define STG_BF 4096             // 128*32 floats
#define STG_STRIDE ((STG_AF + STG_BF) * 4)   // 49152 B per stage
#define SMEM_TOT (OFF_STG + 2 * STG_STRIDE)  // 159744 B

// cp.async fp32 tiles for one K-chunk into staging[stg]
__device__ __forceinline__ void issue_stage(char* sm, int stg,
        const float* __restrict__ A, const float* __restrict__ B,
        int by, int bx, int K, int k0, int tid) {
    float* stA = (float*)(sm + OFF_STG + (size_t)stg * STG_STRIDE);
    float* stB = stA + STG_AF;
#pragma unroll
    for (int i = 0; i < 8; i++) {                 // A: 2048 x 16B
        int idx = tid + 256 * i;
        int row = idx >> 3, seg = idx & 7;
        uint32_t off = (uint32_t)(row * 32 + ((seg ^ (row & 7)) << 2));
        cpa16(stA + off, A + (size_t)(by + row) * K + k0 + seg * 4);
    }
#pragma unroll
    for (int i = 0; i < 4; i++) {                 // B: 1024 x 16B
        int idx = tid + 256 * i;
        int row = idx >> 3, seg = idx & 7;
        uint32_t off = (uint32_t)(row * 32 + ((seg ^ (row & 7)) << 2));
        cpa16(stB + off, B + (size_t)(bx + row) * K + k0 + seg * 4);
    }
}

template <int MODE>
__global__ void __launch_bounds__(256)
gemm_tc(const float* __restrict__ Ag, const float* __restrict__ Bg,
        float* __restrict__ Cg, int K, int dst)
{
    // LOGITS: skip tiles entirely above the diagonal (cols all > rows)
    if (MODE == M_LOGITS && (int)blockIdx.x > 2 * (int)blockIdx.y + 1) return;

    const int h = blockIdx.z;
    const float* A;
    const float* B;
    if (MODE == M_PROJ)        { A = Ag;                           B = Bg; }
    else if (MODE == M_LOGITS) { A = g_Q   + (size_t)h * S * HD;   B = g_K   + (size_t)h * S * HD; }
    else if (MODE == M_SP1)    { A = g_Q   + (size_t)h * S * HD;   B = g_Kk  + (size_t)h * 256 * HD; }
    else if (MODE == M_SP2)    { A = g_awk + (size_t)h * S * 256;  B = g_VkT + (size_t)h * HD * 256; }
    else                       { A = g_outpre;                     B = Bg; }

    extern __shared__ char sm[];
    bf16 (*Ahs)[LDA] = (bf16(*)[LDA])(sm + OFF_AH);
    bf16 (*Als)[LDA] = (bf16(*)[LDA])(sm + OFF_AL);
    bf16 (*Bhs)[LDA] = (bf16(*)[LDA])(sm + OFF_BH);
    bf16 (*Bls)[LDA] = (bf16(*)[LDA])(sm + OFF_BL);

    const int bx = blockIdx.x * 128, by = blockIdx.y * 256;
    const int tid = threadIdx.x, lane = tid & 31, w = tid >> 5;
    const int wm = (w & 3) * 64;       // 4 warp-rows
    const int wn = (w >> 2) * 64;      // 2 warp-cols

    float acc[4][8][4];
#pragma unroll
    for (int i = 0; i < 4; i++)
#pragma unroll
        for (int j = 0; j < 8; j++)
#pragma unroll
            for (int e = 0; e < 4; e++) acc[i][j][e] = 0.f;

    const int nk = K >> 5;

    issue_stage(sm, 0, A, B, by, bx, K, 0, tid);
    asm volatile("cp.async.commit_group;\n");

    for (int c = 0; c < nk; c++) {
        if (c + 1 < nk) {
            issue_stage(sm, (c + 1) & 1, A, B, by, bx, K, (c + 1) * 32, tid);
            asm volatile("cp.async.commit_group;\n");
            asm volatile("cp.async.wait_group 1;\n");
        } else {
            asm volatile("cp.async.wait_group 0;\n");
        }
        __syncthreads();

        // ---- split phase: LDS fp32 staging -> split -> STS bf16 ----
        {
            const float* stA = (const float*)(sm + OFF_STG + (size_t)(c & 1) * STG_STRIDE);
            const float* stB = stA + STG_AF;
            // A: one row per thread, 8 segs
            const int arow = tid;
#pragma unroll
            for (int seg = 0; seg < 8; seg++) {
                const uint32_t off = (uint32_t)(arow * 32 + ((seg ^ (arow & 7)) << 2));
                float4 av = *(const float4*)(stA + off);
                float a4[4] = {av.x, av.y, av.z, av.w};
                float h4[4], l4[4];
#pragma unroll
                for (int t = 0; t < 4; t++) {
                    bf16 hv = __float2bfloat16(a4[t]);
                    h4[t] = __bfloat162float(hv);
                    l4[t] = a4[t] - h4[t];
                }
                uint2 u;
                u.x = pk2(h4[0], h4[1]); u.y = pk2(h4[2], h4[3]);
                *(uint2*)&Ahs[arow][seg * 4] = u;
                u.x = pk2(l4[0], l4[1]); u.y = pk2(l4[2], l4[3]);
                *(uint2*)&Als[arow][seg * 4] = u;
            }
            // B: half row per thread, 4 segs
            const int brow = tid >> 1, s0 = (tid & 1) * 4;
#pragma unroll
            for (int j = 0; j < 4; j++) {
                const int seg = s0 + j;
                const uint32_t off = (uint32_t)(brow * 32 + ((seg ^ (brow & 7)) << 2));
                float4 bv = *(const float4*)(stB + off);
                float b4[4] = {bv.x, bv.y, bv.z, bv.w};
                float h4[4], l4[4];
#pragma unroll
                for (int t = 0; t < 4; t++) {
                    bf16 hv = __float2bfloat16(b4[t]);
                    h4[t] = __bfloat162float(hv);
                    l4[t] = b4[t] - h4[t];
                }
                uint2 u;
                u.x = pk2(h4[0], h4[1]); u.y = pk2(h4[2], h4[3]);
                *(uint2*)&Bhs[brow][seg * 4] = u;
                u.x = pk2(l4[0], l4[1]); u.y = pk2(l4[2], l4[3]);
                *(uint2*)&Bls[brow][seg * 4] = u;
            }
        }
        __syncthreads();

        // ---- mma phase (term-resequenced) ----
#pragma unroll
        for (int kc = 0; kc < 32; kc += 16) {
            uint32_t a1[4][4], a2[4][4], b[8][2];
            const int ar = (lane & 15), ac = kc + (lane >> 4) * 8;
            const int br = (lane & 7) + ((lane >> 4) & 1) * 8, bc = kc + ((lane >> 3) & 1) * 8;
#pragma unroll
            for (int mi = 0; mi < 4; mi++) ldsm4(a1[mi], &Ahs[wm + mi * 16 + ar][ac]);
#pragma unroll
            for (int pi = 0; pi < 4; pi++) ldsm4(&b[2 * pi][0], &Bhs[wn + pi * 16 + br][bc]);
#pragma unroll
            for (int mi = 0; mi < 4; mi++)
#pragma unroll
                for (int ni = 0; ni < 8; ni++) mma16816(acc[mi][ni], a1[mi], b[ni]);   // hh
#pragma unroll
            for (int mi = 0; mi < 4; mi++) ldsm4(a2[mi], &Als[wm + mi * 16 + ar][ac]);
#pragma unroll
            for (int mi = 0; mi < 4; mi++)
#pragma unroll
                for (int ni = 0; ni < 8; ni++) mma16816(acc[mi][ni], a2[mi], b[ni]);   // lh
#pragma unroll
            for (int pi = 0; pi < 4; pi++) ldsm4(&b[2 * pi][0], &Bls[wn + pi * 16 + br][bc]);
#pragma unroll
            for (int mi = 0; mi < 4; mi++)
#pragma unroll
                for (int ni = 0; ni < 8; ni++) mma16816(acc[mi][ni], a1[mi], b[ni]);   // hl
        }
    }
    __syncthreads();

    // ---------------- epilogue ----------------
#pragma unroll
    for (int mi = 0; mi < 4; mi++)
#pragma unroll
        for (int ni = 0; ni < 8; ni++)
#pragma unroll
            for (int e = 0; e < 4; e++) {
                const int row = by + wm + mi * 16 + (lane >> 2) + (e >> 1) * 8;
                const int col = bx + wn + ni * 8 + (lane & 3) * 2 + (e & 1);
                float v = acc[mi][ni][e];
                if (MODE == M_PROJ) {
                    float* D = (dst == 0) ? g_Q : (dst == 1) ? g_K : g_V;
                    D[((size_t)(col >> 7) * S + row) * HD + (col & 127)] = v;
                } else if (MODE == M_LOGITS) {
                    v *= RSQ;
                    if (col > row) v = fmaxf(v + MV, MV);
                    g_AW[((size_t)h * S + row) * S + col] = v;
                } else if (MODE == M_SP1) {
                    if (col < KEEP) {
                        v *= RSQ;
                        int kk = g_kidx[h * KEEP + col];
                        if (kk > row) v = fmaxf(v + MV, MV);
                    } else {
                        v = 0.f;
                    }
                    g_awk[((size_t)h * S + row) * 256 + col] = v;
                } else if (MODE == M_SP2) {
                    v += g_negc[h * HD + col];
                    g_outpre[(size_t)row * HID + h * HD + col] = v;
                } else { // M_FINAL
                    Cg[(size_t)row * HID + col] = v;
                }
            }
}

// ---------------- softmax stats ----------------
__global__ void rowstats_kernel() {
    const int h = blockIdx.y;
    const int q = blockIdx.x * 8 + (threadIdx.x >> 5);
    const int lane = threadIdx.x & 31;
    const float* row = g_AW + ((size_t)h * S + q) * S;
    float m = -3.4e38f, z = 0.f;
    for (int k = lane; k <= q; k += 32) {
        float v = row[k];
        float nm = fmaxf(m, v);
        z = z * __expf(m - nm) + __expf(v - nm);
        m = nm;
    }
#pragma unroll
    for (int off = 16; off > 0; off >>= 1) {
        float om = __shfl_xor_sync(0xffffffffu, m, off);
        float oz = __shfl_xor_sync(0xffffffffu, z, off);
        float nm = fmaxf(m, om);
        z = z * __expf(m - nm) + oz * __expf(om - nm);
        m = nm;
    }
    if (lane == 0) {
        g_rowm[h * S + q] = m;
        g_rowz[h * S + q] = 1.f / z;
    }
}

__global__ void colsum_kernel() {
    const int h = blockIdx.y;
    const int k = blockIdx.x * 256 + threadIdx.x;
    const float* AWh = g_AW + (size_t)h * S * S;
    const float* rm = g_rowm + h * S;
    const float* rz = g_rowz + h * S;
    float acc = 0.f;
    for (int q = blockIdx.x * 256; q < S; q++) {
        float v = AWh[(size_t)q * S + k];
        if (q >= k) acc += __expf(v - rm[q]) * rz[q];
    }
    g_scores[h * S + k] = acc;
}

// ---------------- top-k ----------------
__global__ void topk_kernel() {
    __shared__ unsigned long long key[S];
    const int h = blockIdx.x;
    const int tid = threadIdx.x;
    for (int i = tid; i < S; i += blockDim.x) {
        unsigned long long kk = 0ull;
        if (i < S - 2) {
            unsigned int b = __float_as_uint(g_scores[h * S + i]);
            b = (b & 0x80000000u) ? ~b : (b | 0x80000000u);
            kk = ((unsigned long long)b << 32) | (unsigned int)(S - 1 - i);
        }
        key[i] = kk;
    }
    __syncthreads();
    for (int ksz = 2; ksz <= S; ksz <<= 1)
        for (int j = ksz >> 1; j > 0; j >>= 1) {
            for (int i = tid; i < S; i += blockDim.x) {
                int ixj = i ^ j;
                if (ixj > i) {
                    bool up = ((i & ksz) == 0);
                    unsigned long long a = key[i], b = key[ixj];
                    if (up ? (a > b) : (a < b)) { key[i] = b; key[ixj] = a; }
                }
            }
            __syncthreads();
        }
    for (int j = tid; j < TOPK; j += blockDim.x)
        g_kidx[h * KEEP + j] = (S - 1) - (int)(key[S - 1 - j] & 0xffffffffu);
    if (tid == 0) {
        g_kidx[h * KEEP + TOPK]     = S - 2;
        g_kidx[h * KEEP + TOPK + 1] = S - 1;
    }
}

// ---------------- gather ----------------
__global__ void gather_kernel() {
    const int h = blockIdx.x;
    const int tid = threadIdx.x;
    float* Kk  = g_Kk  + (size_t)h * 256 * HD;
    float* VkT = g_VkT + (size_t)h * HD * 256;
    for (int i = tid; i < 256 * HD; i += 256) { Kk[i] = 0.f; VkT[i] = 0.f; }
    __syncthreads();
    const float* Kh = g_K + (size_t)h * S * HD;
    const float* Vh = g_V + (size_t)h * S * HD;
    for (int i = tid; i < KEEP * HD; i += 256) {
        int j = i / HD, d = i % HD;
        int kk = g_kidx[h * KEEP + j];
        Kk[j * HD + d]   = Kh[(size_t)kk * HD + d];
        VkT[d * 256 + j] = Vh[(size_t)kk * HD + d];
    }
    if (tid < HD) {
        int d = tid;
        float tot = 0.f;
        for (int k = 0; k < S; k++) tot += Vh[(size_t)k * HD + d];
        float kept = 0.f;
        for (int j = 0; j < KEEP; j++)
            kept += Vh[(size_t)g_kidx[h * KEEP + j] * HD + d];
        g_negc[h * HD + d] = MV * (tot - kept);
    }
}

// ---------------- launch ----------------
extern "C" void kernel_launch(void* const* d_in, const int* in_sizes, int n_in,
                              void* d_out, int out_size)
{
    const float* hidden = (const float*)d_in[0];
    const float* Wq = (const float*)d_in[2];
    const float* Wk = (const float*)d_in[3];
    const float* Wv = (const float*)d_in[4];
    const float* Wo = (const float*)d_in[5];
    float* out = (float*)d_out;

    cudaFuncSetAttribute(gemm_tc<M_PROJ>,   cudaFuncAttributeMaxDynamicSharedMemorySize, SMEM_TOT);
    cudaFuncSetAttribute(gemm_tc<M_LOGITS>, cudaFuncAttributeMaxDynamicSharedMemorySize, SMEM_TOT);
    cudaFuncSetAttribute(gemm_tc<M_SP1>,    cudaFuncAttributeMaxDynamicSharedMemorySize, SMEM_TOT);
    cudaFuncSetAttribute(gemm_tc<M_SP2>,    cudaFuncAttributeMaxDynamicSharedMemorySize, SMEM_TOT);
    cudaFuncSetAttribute(gemm_tc<M_FINAL>,  cudaFuncAttributeMaxDynamicSharedMemorySize, SMEM_TOT);

    rope_table_kernel<<<(S * 64 + 255) / 256, 256>>>();

    dim3 g_proj(HID / 128, S / 256, 1);
    gemm_tc<M_PROJ><<<g_proj, 256, SMEM_TOT>>>(hidden, Wq, nullptr, HID, 0);
    gemm_tc<M_PROJ><<<g_proj, 256, SMEM_TOT>>>(hidden, Wk, nullptr, HID, 1);
    gemm_tc<M_PROJ><<<g_proj, 256, SMEM_TOT>>>(hidden, Wv, nullptr, HID, 2);

    rope_apply_kernel<<<(NH * S * 64 + 255) / 256, 256>>>();

    dim3 g_log(S / 128, S / 256, NH);
    gemm_tc<M_LOGITS><<<g_log, 256, SMEM_TOT>>>(nullptr, nullptr, nullptr, HD, 0);

    rowstats_kernel<<<dim3(S / 8, NH), 256>>>();
    colsum_kernel<<<dim3(S / 256, NH), 256>>>();
    topk_kernel<<<NH, 512>>>();
    gather_kernel<<<NH, 256>>>();

    gemm_tc<M_SP1><<<dim3(2, S / 256, NH), 256, SMEM_TOT>>>(nullptr, nullptr, nullptr, HD, 0);
    gemm_tc<M_SP2><<<dim3(1, S / 256, NH), 256, SMEM_TOT>>>(nullptr, nullptr, nullptr, 256, 0);

    dim3 g_fin(HID / 128, S / 256, 1);
    gemm_tc<M_FINAL><<<g_fin, 256, SMEM_TOT>>>(nullptr, Wo, out, HID, 0);
}

// round 12
// speedup vs baseline: 1.0449x; 1.0449x over previous
#include <cuda_runtime.h>
#include <cuda_bf16.h>
#include <math.h>
#include <stdint.h>

#define S    2048
#define NH   32
#define HD   128
#define HID  4096
#define KEEP 206
#define TOPK 204
#define MV   -1000000000.0f
#define RSQ  0.08838834764831845f   /* 1/sqrt(128) */

typedef __nv_bfloat16 bf16;

// ---------------- device scratch ----------------
static __device__ float g_Q[NH * S * HD];
static __device__ float g_K[NH * S * HD];
static __device__ float g_V[NH * S * HD];
static __device__ float g_AW[NH * S * S];          // masked logits (lower tri valid)
static __device__ float g_rowm[NH * S];
static __device__ float g_rowz[NH * S];
static __device__ float g_scores[NH * S];
static __device__ int   g_kidx[NH * KEEP];
static __device__ float g_Kk[NH * 256 * HD];
static __device__ float g_VkT[NH * HD * 256];
static __device__ float g_awk[NH * S * 256];
static __device__ float g_negc[NH * HD];
static __device__ float g_outpre[S * HID];
static __device__ float g_cos[S * 64];
static __device__ float g_sin[S * 64];

// ---------------- RoPE ----------------
__global__ void rope_table_kernel() {
    int idx = blockIdx.x * blockDim.x + threadIdx.x;
    if (idx >= S * 64) return;
    int s = idx >> 6, i = idx & 63;
    double inv = exp(-((double)i / 64.0) * log(10000.0));
    float ph = (float)s * (float)inv;
    g_cos[idx] = cosf(ph);
    g_sin[idx] = sinf(ph);
}

__global__ void rope_apply_kernel() {
    int idx = blockIdx.x * blockDim.x + threadIdx.x;
    if (idx >= NH * S * 64) return;
    int i = idx & 63;
    int s = (idx >> 6) & (S - 1);
    int h = idx >> 17;
    float c  = g_cos[(s << 6) + i];
    float sn = g_sin[(s << 6) + i];
    size_t base = ((size_t)h * S + s) * HD;
    float a = g_Q[base + i], b = g_Q[base + i + 64];
    g_Q[base + i]      = a * c - b * sn;
    g_Q[base + i + 64] = b * c + a * sn;
    a = g_K[base + i]; b = g_K[base + i + 64];
    g_K[base + i]      = a * c - b * sn;
    g_K[base + i + 64] = b * c + a * sn;
}

// ---------------- pipelined tensor-core NT GEMM (R10 config, fused QKV) ----------------
enum { M_PROJ = 0, M_LOGITS = 1, M_SP1 = 2, M_SP2 = 3, M_FINAL = 4 };

__device__ __forceinline__ void ldsm4(uint32_t* r, const void* p) {
    uint32_t addr = (uint32_t)__cvta_generic_to_shared(p);
    asm volatile("ldmatrix.sync.aligned.m8n8.x4.shared.b16 {%0,%1,%2,%3},[%4];\n"
                 : "=r"(r[0]), "=r"(r[1]), "=r"(r[2]), "=r"(r[3]) : "r"(addr));
}
__device__ __forceinline__ void mma16816(float* c, const uint32_t* a, const uint32_t* b) {
    asm volatile("mma.sync.aligned.m16n8k16.row.col.f32.bf16.bf16.f32 "
                 "{%0,%1,%2,%3},{%4,%5,%6,%7},{%8,%9},{%0,%1,%2,%3};\n"
                 : "+f"(c[0]), "+f"(c[1]), "+f"(c[2]), "+f"(c[3])
                 : "r"(a[0]), "r"(a[1]), "r"(a[2]), "r"(a[3]), "r"(b[0]), "r"(b[1]));
}
__device__ __forceinline__ void cpa16(const void* smem, const void* gmem) {
    uint32_t s = (uint32_t)__cvta_generic_to_shared(smem);
    asm volatile("cp.async.ca.shared.global [%0],[%1],16;\n" :: "r"(s), "l"(gmem));
}
__device__ __forceinline__ uint32_t pk2(float a, float b) {
    __nv_bfloat162 t = __float22bfloat162_rn(make_float2(a, b));
    return *(uint32_t*)&t;
}

#define LDA 40                             // bf16 per row (80B), conflict-free ldsm
#define BF_BYTES (4 * 128 * LDA * 2)       // 40960 (Ah|Al|Bh|Bl)
#define STG_F    (128 * 32)                // 4096 floats per operand-stage
#define STG_BYTES (STG_F * 4)              // 16384
#define SMEM_TOT (BF_BYTES + 4 * STG_BYTES)  // 106496

// cp.async fp32 tiles (A,B) for one chunk into staging[stg]
__device__ __forceinline__ void issue_stage(char* sm, int stg,
        const float* __restrict__ A, const float* __restrict__ B,
        int by, int bxl, int K, int k0, int tid) {
    float* stA = (float*)(sm + BF_BYTES + (size_t)stg * 2 * STG_BYTES);
    float* stB = stA + STG_F;
#pragma unroll
    for (int i = 0; i < 4; i++) {
        int idx = tid + 256 * i;           // 0..1023
        int row = idx >> 3, seg = idx & 7;
        uint32_t off = (uint32_t)(row * 32 + ((seg ^ (row & 7)) << 2));
        cpa16(stA + off, A + (size_t)(by + row) * K + k0 + seg * 4);
        cpa16(stB + off, B + (size_t)(bxl + row) * K + k0 + seg * 4);
    }
}

template <int MODE>
__global__ void __launch_bounds__(256, 2)
gemm_tc(const float* __restrict__ Ag, const float* __restrict__ Bg,
        const float* __restrict__ Bg2, const float* __restrict__ Bg3,
        float* __restrict__ Cg, int K)
{
    if (MODE == M_LOGITS && blockIdx.x > blockIdx.y) return;  // strict upper never read

    const int h = blockIdx.z;
    const float* A;
    const float* B;
    const int bx = blockIdx.x * 128, by = blockIdx.y * 128;
    int bxl = bx;   // local B row origin (differs from bx only for fused PROJ)

    if (MODE == M_PROJ) {
        A = Ag;
        const int panel = blockIdx.x >> 5;           // 0:Wq 1:Wk 2:Wv
        B = (panel == 0) ? Bg : (panel == 1) ? Bg2 : Bg3;
        bxl = (blockIdx.x & 31) * 128;
    }
    else if (MODE == M_LOGITS) { A = g_Q   + (size_t)h * S * HD;   B = g_K   + (size_t)h * S * HD; }
    else if (MODE == M_SP1)    { A = g_Q   + (size_t)h * S * HD;   B = g_Kk  + (size_t)h * 256 * HD; }
    else if (MODE == M_SP2)    { A = g_awk + (size_t)h * S * 256;  B = g_VkT + (size_t)h * HD * 256; }
    else                       { A = g_outpre;                     B = Bg; }

    extern __shared__ char sm[];
    bf16 (*Ahs)[LDA] = (bf16(*)[LDA])(sm);
    bf16 (*Als)[LDA] = (bf16(*)[LDA])(sm + 10240);
    bf16 (*Bhs)[LDA] = (bf16(*)[LDA])(sm + 20480);
    bf16 (*Bls)[LDA] = (bf16(*)[LDA])(sm + 30720);

    const int tid = threadIdx.x, lane = tid & 31, w = tid >> 5;
    const int wm = (w & 1) * 64;
    const int wn = (w >> 1) * 32;

    float acc[4][4][4];
#pragma unroll
    for (int i = 0; i < 4; i++)
#pragma unroll
        for (int j = 0; j < 4; j++)
#pragma unroll
            for (int e = 0; e < 4; e++) acc[i][j][e] = 0.f;

    const int nk = K >> 5;

    issue_stage(sm, 0, A, B, by, bxl, K, 0, tid);
    asm volatile("cp.async.commit_group;\n");

    for (int c = 0; c < nk; c++) {
        if (c + 1 < nk) {
            issue_stage(sm, (c + 1) & 1, A, B, by, bxl, K, (c + 1) * 32, tid);
            asm volatile("cp.async.commit_group;\n");
            asm volatile("cp.async.wait_group 1;\n");
        } else {
            asm volatile("cp.async.wait_group 0;\n");
        }
        __syncthreads();   // staging[c] visible; mma(c-1) done -> bf16 arrays free

        // ---- split phase: LDS fp32 staging -> split -> STS bf16 arrays ----
        {
            const float* stA = (const float*)(sm + BF_BYTES + (size_t)(c & 1) * 2 * STG_BYTES);
            const float* stB = stA + STG_F;
            const int lr = tid >> 1, s0 = (tid & 1) * 4;
#pragma unroll
            for (int j = 0; j < 4; j++) {
                const int seg = s0 + j;
                const uint32_t off = (uint32_t)(lr * 32 + ((seg ^ (lr & 7)) << 2));
                float4 av = *(const float4*)(stA + off);
                float4 bv = *(const float4*)(stB + off);
                float a4[4] = {av.x, av.y, av.z, av.w};
                float b4[4] = {bv.x, bv.y, bv.z, bv.w};
                float ah4[4], al4[4], bh4[4], bl4[4];
#pragma unroll
                for (int t = 0; t < 4; t++) {
                    bf16 hv = __float2bfloat16(a4[t]);
                    ah4[t] = __bfloat162float(hv);
                    al4[t] = a4[t] - ah4[t];
                    hv = __float2bfloat16(b4[t]);
                    bh4[t] = __bfloat162float(hv);
                    bl4[t] = b4[t] - bh4[t];
                }
                uint2 u;
                u.x = pk2(ah4[0], ah4[1]); u.y = pk2(ah4[2], ah4[3]);
                *(uint2*)&Ahs[lr][seg * 4] = u;
                u.x = pk2(al4[0], al4[1]); u.y = pk2(al4[2], al4[3]);
                *(uint2*)&Als[lr][seg * 4] = u;
                u.x = pk2(bh4[0], bh4[1]); u.y = pk2(bh4[2], bh4[3]);
                *(uint2*)&Bhs[lr][seg * 4] = u;
                u.x = pk2(bl4[0], bl4[1]); u.y = pk2(bl4[2], bl4[3]);
                *(uint2*)&Bls[lr][seg * 4] = u;
            }
        }
        __syncthreads();

        // ---- mma phase (term-resequenced: peak 40 live frags) ----
#pragma unroll
        for (int kc = 0; kc < 32; kc += 16) {
            uint32_t a1[4][4], a2[4][4], b[4][2];
            const int ar = (lane & 15), ac = kc + (lane >> 4) * 8;
            const int br = (lane & 7) + ((lane >> 4) & 1) * 8, bc = kc + ((lane >> 3) & 1) * 8;
#pragma unroll
            for (int mi = 0; mi < 4; mi++) ldsm4(a1[mi], &Ahs[wm + mi * 16 + ar][ac]);
#pragma unroll
            for (int pi = 0; pi < 2; pi++) ldsm4(&b[2 * pi][0], &Bhs[wn + pi * 16 + br][bc]);
#pragma unroll
            for (int mi = 0; mi < 4; mi++)
#pragma unroll
                for (int ni = 0; ni < 4; ni++) mma16816(acc[mi][ni], a1[mi], b[ni]);   // hh
#pragma unroll
            for (int mi = 0; mi < 4; mi++) ldsm4(a2[mi], &Als[wm + mi * 16 + ar][ac]);
#pragma unroll
            for (int mi = 0; mi < 4; mi++)
#pragma unroll
                for (int ni = 0; ni < 4; ni++) mma16816(acc[mi][ni], a2[mi], b[ni]);   // lh
#pragma unroll
            for (int pi = 0; pi < 2; pi++) ldsm4(&b[2 * pi][0], &Bls[wn + pi * 16 + br][bc]);
#pragma unroll
            for (int mi = 0; mi < 4; mi++)
#pragma unroll
                for (int ni = 0; ni < 4; ni++) mma16816(acc[mi][ni], a1[mi], b[ni]);   // hl
        }
    }
    __syncthreads();

    // ---------------- epilogue ----------------
#pragma unroll
    for (int mi = 0; mi < 4; mi++)
#pragma unroll
        for (int ni = 0; ni < 4; ni++)
#pragma unroll
            for (int e = 0; e < 4; e++) {
                const int row = by + wm + mi * 16 + (lane >> 2) + (e >> 1) * 8;
                const int col = bx + wn + ni * 8 + (lane & 3) * 2 + (e & 1);
                float v = acc[mi][ni][e];
                if (MODE == M_PROJ) {
                    const int which = col >> 12, inner = col & 4095;
                    float* D = (which == 0) ? g_Q : (which == 1) ? g_K : g_V;
                    D[((size_t)(inner >> 7) * S + row) * HD + (inner & 127)] = v;
                } else if (MODE == M_LOGITS) {
                    v *= RSQ;
                    if (col > row) v = fmaxf(v + MV, MV);
                    g_AW[((size_t)h * S + row) * S + col] = v;
                } else if (MODE == M_SP1) {
                    if (col < KEEP) {
                        v *= RSQ;
                        int kk = g_kidx[h * KEEP + col];
                        if (kk > row) v = fmaxf(v + MV, MV);
                    } else {
                        v = 0.f;
                    }
                    g_awk[((size_t)h * S + row) * 256 + col] = v;
                } else if (MODE == M_SP2) {
                    v += g_negc[h * HD + col];
                    g_outpre[(size_t)row * HID + h * HD + col] = v;
                } else { // M_FINAL
                    Cg[(size_t)row * HID + col] = v;
                }
            }
}

// ---------------- softmax stats ----------------
__global__ void rowstats_kernel() {
    const int h = blockIdx.y;
    const int q = blockIdx.x * 8 + (threadIdx.x >> 5);
    const int lane = threadIdx.x & 31;
    const float* row = g_AW + ((size_t)h * S + q) * S;
    float m = -3.4e38f, z = 0.f;
    for (int k = lane; k <= q; k += 32) {
        float v = row[k];
        float nm = fmaxf(m, v);
        z = z * __expf(m - nm) + __expf(v - nm);
        m = nm;
    }
#pragma unroll
    for (int off = 16; off > 0; off >>= 1) {
        float om = __shfl_xor_sync(0xffffffffu, m, off);
        float oz = __shfl_xor_sync(0xffffffffu, z, off);
        float nm = fmaxf(m, om);
        z = z * __expf(m - nm) + oz * __expf(om - nm);
        m = nm;
    }
    if (lane == 0) {
        g_rowm[h * S + q] = m;
        g_rowz[h * S + q] = 1.f / z;
    }
}

__global__ void colsum_kernel() {
    const int h = blockIdx.y;
    const int k = blockIdx.x * 256 + threadIdx.x;
    const float* AWh = g_AW + (size_t)h * S * S;
    const float* rm = g_rowm + h * S;
    const float* rz = g_rowz + h * S;
    float acc = 0.f;
    for (int q = blockIdx.x * 256; q < S; q++) {
        float v = AWh[(size_t)q * S + k];
        if (q >= k) acc += __expf(v - rm[q]) * rz[q];
    }
    g_scores[h * S + k] = acc;
}

// ---------------- top-k ----------------
__global__ void topk_kernel() {
    __shared__ unsigned long long key[S];
    const int h = blockIdx.x;
    const int tid = threadIdx.x;
    for (int i = tid; i < S; i += blockDim.x) {
        unsigned long long kk = 0ull;
        if (i < S - 2) {
            unsigned int b = __float_as_uint(g_scores[h * S + i]);
            b = (b & 0x80000000u) ? ~b : (b | 0x80000000u);
            kk = ((unsigned long long)b << 32) | (unsigned int)(S - 1 - i);
        }
        key[i] = kk;
    }
    __syncthreads();
    for (int ksz = 2; ksz <= S; ksz <<= 1)
        for (int j = ksz >> 1; j > 0; j >>= 1) {
            for (int i = tid; i < S; i += blockDim.x) {
                int ixj = i ^ j;
                if (ixj > i) {
                    bool up = ((i & ksz) == 0);
                    unsigned long long a = key[i], b = key[ixj];
                    if (up ? (a > b) : (a < b)) { key[i] = b; key[ixj] = a; }
                }
            }
            __syncthreads();
        }
    for (int j = tid; j < TOPK; j += blockDim.x)
        g_kidx[h * KEEP + j] = (S - 1) - (int)(key[S - 1 - j] & 0xffffffffu);
    if (tid == 0) {
        g_kidx[h * KEEP + TOPK]     = S - 2;
        g_kidx[h * KEEP + TOPK + 1] = S - 1;
    }
}

// ---------------- gather ----------------
__global__ void gather_kernel() {
    const int h = blockIdx.x;
    const int tid = threadIdx.x;
    float* Kk  = g_Kk  + (size_t)h * 256 * HD;
    float* VkT = g_VkT + (size_t)h * HD * 256;
    for (int i = tid; i < 256 * HD; i += 256) { Kk[i] = 0.f; VkT[i] = 0.f; }
    __syncthreads();
    const float* Kh = g_K + (size_t)h * S * HD;
    const float* Vh = g_V + (size_t)h * S * HD;
    for (int i = tid; i < KEEP * HD; i += 256) {
        int j = i / HD, d = i % HD;
        int kk = g_kidx[h * KEEP + j];
        Kk[j * HD + d]   = Kh[(size_t)kk * HD + d];
        VkT[d * 256 + j] = Vh[(size_t)kk * HD + d];
    }
    if (tid < HD) {
        int d = tid;
        float tot = 0.f;
        for (int k = 0; k < S; k++) tot += Vh[(size_t)k * HD + d];
        float kept = 0.f;
        for (int j = 0; j < KEEP; j++)
            kept += Vh[(size_t)g_kidx[h * KEEP + j] * HD + d];
        g_negc[h * HD + d] = MV * (tot - kept);
    }
}

// ---------------- launch ----------------
extern "C" void kernel_launch(void* const* d_in, const int* in_sizes, int n_in,
                              void* d_out, int out_size)
{
    const float* hidden = (const float*)d_in[0];
    const float* Wq = (const float*)d_in[2];
    const float* Wk = (const float*)d_in[3];
    const float* Wv = (const float*)d_in[4];
    const float* Wo = (const float*)d_in[5];
    float* out = (float*)d_out;

    cudaFuncSetAttribute(gemm_tc<M_PROJ>,   cudaFuncAttributeMaxDynamicSharedMemorySize, SMEM_TOT);
    cudaFuncSetAttribute(gemm_tc<M_LOGITS>, cudaFuncAttributeMaxDynamicSharedMemorySize, SMEM_TOT);
    cudaFuncSetAttribute(gemm_tc<M_SP1>,    cudaFuncAttributeMaxDynamicSharedMemorySize, SMEM_TOT);
    cudaFuncSetAttribute(gemm_tc<M_SP2>,    cudaFuncAttributeMaxDynamicSharedMemorySize, SMEM_TOT);
    cudaFuncSetAttribute(gemm_tc<M_FINAL>,  cudaFuncAttributeMaxDynamicSharedMemorySize, SMEM_TOT);

    rope_table_kernel<<<(S * 64 + 255) / 256, 256>>>();

    // fused QKV projection: M=2048, N=12288 (3 panels), K=4096 -> one launch, 5.2 waves
    dim3 g_proj(3 * HID / 128, S / 128, 1);
    gemm_tc<M_PROJ><<<g_proj, 256, SMEM_TOT>>>(hidden, Wq, Wk, Wv, nullptr, HID);

    rope_apply_kernel<<<(NH * S * 64 + 255) / 256, 256>>>();

    dim3 g_log(S / 128, S / 128, NH);
    gemm_tc<M_LOGITS><<<g_log, 256, SMEM_TOT>>>(nullptr, nullptr, nullptr, nullptr, nullptr, HD);

    rowstats_kernel<<<dim3(S / 8, NH), 256>>>();
    colsum_kernel<<<dim3(S / 256, NH), 256>>>();
    topk_kernel<<<NH, 512>>>();
    gather_kernel<<<NH, 256>>>();

    gemm_tc<M_SP1><<<dim3(2, S / 128, NH), 256, SMEM_TOT>>>(nullptr, nullptr, nullptr, nullptr, nullptr, HD);
    gemm_tc<M_SP2><<<dim3(1, S / 128, NH), 256, SMEM_TOT>>>(nullptr, nullptr, nullptr, nullptr, nullptr, 256);

    dim3 g_fin(HID / 128, S / 128, 1);
    gemm_tc<M_FINAL><<<g_fin, 256, SMEM_TOT>>>(nullptr, Wo, nullptr, nullptr, out, HID);
}